// round 17
// baseline (speedup 1.0000x reference)
#include <cuda_runtime.h>
#include <cuda_bf16.h>
#include <cuda_fp16.h>
#include <cstdint>
#include <math.h>

// Problem constants
#define NB 4
#define NQ 2048
#define NK 2048
#define ND 1024

// ---------------------------------------------------------------------------
// Device scratch
// ---------------------------------------------------------------------------
__device__ static float g_scores[(size_t)NB * NQ * NK];
__device__ static __nv_bfloat16 g_qhi[(size_t)NB * NQ * ND];
__device__ static __nv_bfloat16 g_qlo[(size_t)NB * NQ * ND];
__device__ static __nv_bfloat16 g_vhi[(size_t)NB * NK * ND];
__device__ static __nv_bfloat16 g_vlo[(size_t)NB * NK * ND];
__device__ static __half g_vthi[(size_t)NB * ND * NK];       // V^T fp16 hi
__device__ static __half g_vtlo[(size_t)NB * ND * NK];       // V^T fp16 lo
__device__ static __half g_phi[(size_t)NB * NQ * NK];        // P fp16 (hi only)

// ---------------------------------------------------------------------------
// split helpers
// ---------------------------------------------------------------------------
__device__ __forceinline__ void split1(float x, __nv_bfloat16& h, __nv_bfloat16& l) {
    h = __float2bfloat16(x);
    l = __float2bfloat16(x - __bfloat162float(h));
}

__device__ __forceinline__ void split1h(float x, __half& h, __half& l) {
    h = __float2half_rn(x);
    l = __float2half_rn(x - __half2float(h));
}

__device__ __forceinline__ void split_store4(__nv_bfloat16* hp, __nv_bfloat16* lp, float4 v) {
    __nv_bfloat16 h0, h1, h2, h3, l0, l1, l2, l3;
    split1(v.x, h0, l0); split1(v.y, h1, l1);
    split1(v.z, h2, l2); split1(v.w, h3, l3);
    __nv_bfloat162 ha; ha.x = h0; ha.y = h1;
    __nv_bfloat162 hb; hb.x = h2; hb.y = h3;
    __nv_bfloat162 la; la.x = l0; la.y = l1;
    __nv_bfloat162 lb; lb.x = l2; lb.y = l3;
    *(__nv_bfloat162*)(hp)     = ha;
    *(__nv_bfloat162*)(hp + 2) = hb;
    *(__nv_bfloat162*)(lp)     = la;
    *(__nv_bfloat162*)(lp + 2) = lb;
}

__device__ __forceinline__ void h_store4(__half* hp, float4 v) {
    __half2 a = __floats2half2_rn(v.x, v.y);
    __half2 b = __floats2half2_rn(v.z, v.w);
    *(__half2*)(hp)     = a;
    *(__half2*)(hp + 2) = b;
}

// ---------------------------------------------------------------------------
// Elementwise split (Q) -> bf16 hi/lo
// ---------------------------------------------------------------------------
__global__ __launch_bounds__(256)
void split_kernel(const float4* __restrict__ in, __nv_bfloat16* __restrict__ hi,
                  __nv_bfloat16* __restrict__ lo) {
    int i = blockIdx.x * 256 + threadIdx.x;
    float4 v = in[i];
    split_store4(hi + (size_t)i * 4, lo + (size_t)i * 4, v);
}

// ---------------------------------------------------------------------------
// Fused V: bf16 hi/lo row-major (GEMM1 B) + fp16 hi/lo transposed (GEMM2 B)
// ---------------------------------------------------------------------------
__global__ __launch_bounds__(256)
void v_split_transpose_kernel(const float* __restrict__ V,
                              __nv_bfloat16* __restrict__ vhi,
                              __nv_bfloat16* __restrict__ vlo,
                              __half* __restrict__ vthi,
                              __half* __restrict__ vtlo) {
    __shared__ float tile[32][33];
    const int b = blockIdx.z;
    const int k0 = blockIdx.y * 32;
    const int d0 = blockIdx.x * 32;
    const int tx = threadIdx.x & 31;
    const int ty = threadIdx.x >> 5;
    const float* Vb = V + (size_t)b * NK * ND;
    __nv_bfloat16* Hr = vhi + (size_t)b * NK * ND;
    __nv_bfloat16* Lr = vlo + (size_t)b * NK * ND;

    #pragma unroll
    for (int r = ty; r < 32; r += 8) {
        float x = Vb[(size_t)(k0 + r) * ND + d0 + tx];
        tile[r][tx] = x;
        __nv_bfloat16 h, l;
        split1(x, h, l);
        size_t o = (size_t)(k0 + r) * ND + d0 + tx;
        Hr[o] = h;
        Lr[o] = l;
    }
    __syncthreads();

    __half* Ht = vthi + (size_t)b * ND * NK;
    __half* Lt = vtlo + (size_t)b * ND * NK;
    #pragma unroll
    for (int r = ty; r < 32; r += 8) {
        float x = tile[tx][r];
        __half h, l;
        split1h(x, h, l);
        size_t o = (size_t)(d0 + r) * NK + k0 + tx;
        Ht[o] = h;
        Lt[o] = l;
    }
}

// ---------------------------------------------------------------------------
// Row softmax over g_scores; emits fp16 P (hi only)
// ---------------------------------------------------------------------------
__global__ __launch_bounds__(256)
void softmax_kernel(__half* __restrict__ phi) {
    const size_t row = blockIdx.x;
    float* p = g_scores + row * (size_t)NK;
    float4* p4 = (float4*)p;
    const int tid = threadIdx.x;
    const int lane = tid & 31;
    const int warp = tid >> 5;

    __shared__ float red[8];

    float4 v0 = p4[tid];
    float4 v1 = p4[tid + 256];

    float m = fmaxf(fmaxf(fmaxf(v0.x, v0.y), fmaxf(v0.z, v0.w)),
                    fmaxf(fmaxf(v1.x, v1.y), fmaxf(v1.z, v1.w)));
    #pragma unroll
    for (int off = 16; off > 0; off >>= 1)
        m = fmaxf(m, __shfl_xor_sync(0xffffffffu, m, off));
    if (lane == 0) red[warp] = m;
    __syncthreads();
    float rowmax = red[0];
    #pragma unroll
    for (int w = 1; w < 8; w++) rowmax = fmaxf(rowmax, red[w]);
    __syncthreads();

    v0.x = expf(v0.x - rowmax); v0.y = expf(v0.y - rowmax);
    v0.z = expf(v0.z - rowmax); v0.w = expf(v0.w - rowmax);
    v1.x = expf(v1.x - rowmax); v1.y = expf(v1.y - rowmax);
    v1.z = expf(v1.z - rowmax); v1.w = expf(v1.w - rowmax);

    float s = (v0.x + v0.y + v0.z + v0.w) + (v1.x + v1.y + v1.z + v1.w);
    #pragma unroll
    for (int off = 16; off > 0; off >>= 1)
        s += __shfl_xor_sync(0xffffffffu, s, off);
    if (lane == 0) red[warp] = s;
    __syncthreads();
    float rowsum = 0.0f;
    #pragma unroll
    for (int w = 0; w < 8; w++) rowsum += red[w];

    const float inv = 1.0f / rowsum;
    v0.x *= inv; v0.y *= inv; v0.z *= inv; v0.w *= inv;
    v1.x *= inv; v1.y *= inv; v1.z *= inv; v1.w *= inv;

    __half* H = phi + row * (size_t)NK;
    h_store4(H + 4 * tid,         v0);
    h_store4(H + 4 * (tid + 256), v1);
}

// ---------------------------------------------------------------------------
// Common GEMM defs
// ---------------------------------------------------------------------------
#define KCH 32
#define SROWB 80                       // padded row stride (bytes)
#define ATILE_B (128 * SROWB)          // 10240 B (128-row operand tile)
#define BTILE_B (256 * SROWB)          // 20480 B (256-row operand tile)

__device__ __forceinline__ void mma_bf16(float* d, const uint32_t* a, const uint32_t* b) {
    asm volatile(
        "mma.sync.aligned.m16n8k16.row.col.f32.bf16.bf16.f32 "
        "{%0,%1,%2,%3}, {%4,%5,%6,%7}, {%8,%9}, {%0,%1,%2,%3};"
        : "+f"(d[0]), "+f"(d[1]), "+f"(d[2]), "+f"(d[3])
        : "r"(a[0]), "r"(a[1]), "r"(a[2]), "r"(a[3]), "r"(b[0]), "r"(b[1]));
}

__device__ __forceinline__ void mma_f16(float* d, const uint32_t* a, const uint32_t* b) {
    asm volatile(
        "mma.sync.aligned.m16n8k16.row.col.f32.f16.f16.f32 "
        "{%0,%1,%2,%3}, {%4,%5,%6,%7}, {%8,%9}, {%0,%1,%2,%3};"
        : "+f"(d[0]), "+f"(d[1]), "+f"(d[2]), "+f"(d[3])
        : "r"(a[0]), "r"(a[1]), "r"(a[2]), "r"(a[3]), "r"(b[0]), "r"(b[1]));
}

__device__ __forceinline__ void ldsm_x4(uint32_t* r, uint32_t addr) {
    asm volatile("ldmatrix.sync.aligned.m8n8.x4.shared.b16 {%0,%1,%2,%3}, [%4];"
                 : "=r"(r[0]), "=r"(r[1]), "=r"(r[2]), "=r"(r[3]) : "r"(addr));
}

__device__ __forceinline__ void cp_async16(uint32_t sdst, const void* gsrc) {
    asm volatile("cp.async.cg.shared.global [%0], [%1], 16;" :: "r"(sdst), "l"(gsrc));
}

__device__ __forceinline__ uint32_t smem_u32(const void* p) {
    uint32_t a;
    asm("{ .reg .u64 t; cvta.to.shared.u64 t, %1; cvt.u32.u64 %0, t; }"
        : "=r"(a) : "l"(p));
    return a;
}

// ---------------------------------------------------------------------------
// GEMM1 (R12 config): bf16 3-pass, CTA 128x256, 8 warps 64x64, 3-stage.
// ---------------------------------------------------------------------------
#define G1_STAGE_B (2 * ATILE_B + 2 * BTILE_B)   // 61440 B
#define G1_NSTAGE 3
#define G1_SMEM (G1_NSTAGE * G1_STAGE_B)          // 184320 B
#define G1_AH 0
#define G1_AL ATILE_B
#define G1_BH (2 * ATILE_B)
#define G1_BL (2 * ATILE_B + BTILE_B)

__global__ __launch_bounds__(256, 1)
void hmma_gemm1_kernel(const __nv_bfloat16* __restrict__ Ahi,
                       const __nv_bfloat16* __restrict__ Alo,
                       const __nv_bfloat16* __restrict__ Bhi,
                       const __nv_bfloat16* __restrict__ Blo,
                       float* __restrict__ C,
                       int Kd, int N) {
    extern __shared__ __nv_bfloat16 sm[];
    const uint32_t smem_base = smem_u32(sm);
    const int tid = threadIdx.x;
    const int wid = tid >> 5;
    const int lane = tid & 31;
    const int group = lane >> 2;
    const int tig = lane & 3;
    const int b = blockIdx.z;
    const int m0 = blockIdx.y * 128;
    const int n0 = blockIdx.x * 256;
    const int wm = (wid & 1) * 64;
    const int wn = (wid >> 1) * 64;

    const __nv_bfloat16* Asrc[2];
    const __nv_bfloat16* Bsrc[2];
    Asrc[0] = Ahi + (size_t)b * 2048 * Kd;
    Asrc[1] = Alo + (size_t)b * 2048 * Kd;
    Bsrc[0] = Bhi + (size_t)b * (size_t)N * Kd;
    Bsrc[1] = Blo + (size_t)b * (size_t)N * Kd;

    float acc[4][8][4];
    #pragma unroll
    for (int i = 0; i < 4; i++)
        #pragma unroll
        for (int j = 0; j < 8; j++)
            #pragma unroll
            for (int r = 0; r < 4; r++) acc[i][j][r] = 0.0f;

    const int lr = lane & 7;
    const int a_moff = ((lane >> 3) & 1) * 8 + lr;
    const int a_koff = (lane >> 4) * 16;
    const int b_noff = (lane >> 4) * 8 + lr;
    const int b_koff = ((lane >> 3) & 1) * 16;

    uint32_t aoff[4], boff[4];
    #pragma unroll
    for (int mt = 0; mt < 4; ++mt)
        aoff[mt] = (uint32_t)((wm + mt * 16 + a_moff) * SROWB + a_koff);
    #pragma unroll
    for (int p = 0; p < 4; ++p)
        boff[p] = (uint32_t)((wn + p * 16 + b_noff) * SROWB + b_koff);

    const int nch = Kd / KCH;

    auto load_chunk = [&](int ci, int stage) {
        const int k0 = ci * KCH;
        const uint32_t s0 = smem_base + (uint32_t)stage * G1_STAGE_B;
        #pragma unroll
        for (int j = 0; j < 4; ++j) {
            int idx = tid + j * 256;
            int T   = idx >> 9;
            int rem = idx & 511;
            int row = rem >> 2;
            int c   = rem & 3;
            cp_async16(s0 + (uint32_t)(T * ATILE_B + row * SROWB + c * 16),
                       Asrc[T] + (size_t)(m0 + row) * Kd + k0 + c * 8);
        }
        #pragma unroll
        for (int j = 0; j < 8; ++j) {
            int idx = tid + j * 256;
            int T   = idx >> 10;
            int rem = idx & 1023;
            int row = rem >> 2;
            int c   = rem & 3;
            cp_async16(s0 + (uint32_t)(G1_BH + T * BTILE_B + row * SROWB + c * 16),
                       Bsrc[T] + (size_t)(n0 + row) * Kd + k0 + c * 8);
        }
        asm volatile("cp.async.commit_group;" ::: "memory");
    };

    load_chunk(0, 0);
    if (nch > 1) load_chunk(1, 1);

    int st = 0;
    int ls = 2 % G1_NSTAGE;

    for (int i = 0; i < nch; ++i) {
        if (i + 1 < nch)
            asm volatile("cp.async.wait_group 1;" ::: "memory");
        else
            asm volatile("cp.async.wait_group 0;" ::: "memory");
        __syncthreads();
        if (i + 2 < nch) {
            load_chunk(i + 2, ls);
            ls = (ls + 1 == G1_NSTAGE) ? 0 : ls + 1;
        }

        const uint32_t sb  = smem_base + (uint32_t)st * G1_STAGE_B;
        const uint32_t sAh = sb + G1_AH;
        const uint32_t sAl = sb + G1_AL;
        const uint32_t sBh = sb + G1_BH;
        const uint32_t sBl = sb + G1_BL;

        #pragma unroll
        for (int ks = 0; ks < 2; ++ks) {
            const uint32_t kadd = (uint32_t)(ks * 32);

            uint32_t ah[4][4], al[4][4], bh[4][4], bl[4][4];
            #pragma unroll
            for (int mt = 0; mt < 4; ++mt) {
                ldsm_x4(ah[mt], sAh + aoff[mt] + kadd);
                ldsm_x4(al[mt], sAl + aoff[mt] + kadd);
            }
            #pragma unroll
            for (int p = 0; p < 4; ++p) {
                ldsm_x4(bh[p], sBh + boff[p] + kadd);
                ldsm_x4(bl[p], sBl + boff[p] + kadd);
            }

            #pragma unroll
            for (int p = 0; p < 4; ++p)
                #pragma unroll
                for (int mt = 0; mt < 4; ++mt) {
                    mma_bf16(acc[mt][2 * p],     ah[mt], &bh[p][0]);
                    mma_bf16(acc[mt][2 * p + 1], ah[mt], &bh[p][2]);
                }
            #pragma unroll
            for (int p = 0; p < 4; ++p)
                #pragma unroll
                for (int mt = 0; mt < 4; ++mt) {
                    mma_bf16(acc[mt][2 * p],     ah[mt], &bl[p][0]);
                    mma_bf16(acc[mt][2 * p + 1], ah[mt], &bl[p][2]);
                }
            #pragma unroll
            for (int p = 0; p < 4; ++p)
                #pragma unroll
                for (int mt = 0; mt < 4; ++mt) {
                    mma_bf16(acc[mt][2 * p],     al[mt], &bh[p][0]);
                    mma_bf16(acc[mt][2 * p + 1], al[mt], &bh[p][2]);
                }
        }

        st = (st + 1 == G1_NSTAGE) ? 0 : st + 1;
    }

    float* Cb = C + (size_t)b * 2048 * (size_t)N;
    #pragma unroll
    for (int mt = 0; mt < 4; ++mt) {
        const int row = m0 + wm + mt * 16 + group;
        #pragma unroll
        for (int nt = 0; nt < 8; ++nt) {
            const int col = n0 + wn + nt * 8 + 2 * tig;
            float2 lo2, hi2;
            lo2.x = acc[mt][nt][0]; lo2.y = acc[mt][nt][1];
            hi2.x = acc[mt][nt][2]; hi2.y = acc[mt][nt][3];
            *(float2*)(Cb + (size_t)row * N + col)       = lo2;
            *(float2*)(Cb + (size_t)(row + 8) * N + col) = hi2;
        }
    }
}

// ---------------------------------------------------------------------------
// GEMM2: fp16 2-pass (Ph*Vhi + Ph*Vlo), CTA 128x256, 8 warps 64x64, 3-stage.
// Stage = A(128r) + Bh(256r) + Bl(256r) = 51200 B.
// ---------------------------------------------------------------------------
#define G2_STAGE_B (ATILE_B + 2 * BTILE_B)       // 51200 B
#define G2_NSTAGE 3
#define G2_SMEM (G2_NSTAGE * G2_STAGE_B)          // 153600 B
#define G2_A  0
#define G2_BH ATILE_B
#define G2_BL (ATILE_B + BTILE_B)

__global__ __launch_bounds__(256, 1)
void hmma_gemm2_kernel(const __half* __restrict__ Ph,
                       const __half* __restrict__ Bhi,
                       const __half* __restrict__ Blo,
                       float* __restrict__ C,
                       int Kd, int N) {
    extern __shared__ __nv_bfloat16 smraw[];
    const uint32_t smem_base = smem_u32(smraw);
    const int tid = threadIdx.x;
    const int wid = tid >> 5;
    const int lane = tid & 31;
    const int group = lane >> 2;
    const int tig = lane & 3;
    const int b = blockIdx.z;
    const int m0 = blockIdx.y * 128;
    const int n0 = blockIdx.x * 256;
    const int wm = (wid & 1) * 64;
    const int wn = (wid >> 1) * 64;

    const __half* A0 = Ph + (size_t)b * 2048 * Kd;
    const __half* Bsrc[2];
    Bsrc[0] = Bhi + (size_t)b * (size_t)N * Kd;
    Bsrc[1] = Blo + (size_t)b * (size_t)N * Kd;

    float acc[4][8][4];
    #pragma unroll
    for (int i = 0; i < 4; i++)
        #pragma unroll
        for (int j = 0; j < 8; j++)
            #pragma unroll
            for (int r = 0; r < 4; r++) acc[i][j][r] = 0.0f;

    const int lr = lane & 7;
    const int a_moff = ((lane >> 3) & 1) * 8 + lr;
    const int a_koff = (lane >> 4) * 16;
    const int b_noff = (lane >> 4) * 8 + lr;
    const int b_koff = ((lane >> 3) & 1) * 16;

    uint32_t aoff[4], boff[4];
    #pragma unroll
    for (int mt = 0; mt < 4; ++mt)
        aoff[mt] = (uint32_t)((wm + mt * 16 + a_moff) * SROWB + a_koff);
    #pragma unroll
    for (int p = 0; p < 4; ++p)
        boff[p] = (uint32_t)((wn + p * 16 + b_noff) * SROWB + b_koff);

    const int nch = Kd / KCH;

    // loads per chunk: A 512 + B 2048 = 2560 ops, 10 per thread
    auto load_chunk = [&](int ci, int stage) {
        const int k0 = ci * KCH;
        const uint32_t s0 = smem_base + (uint32_t)stage * G2_STAGE_B;
        #pragma unroll
        for (int j = 0; j < 2; ++j) {
            int idx = tid + j * 256;       // 0..511
            int row = idx >> 2;            // 0..127
            int c   = idx & 3;
            cp_async16(s0 + (uint32_t)(G2_A + row * SROWB + c * 16),
                       A0 + (size_t)(m0 + row) * Kd + k0 + c * 8);
        }
        #pragma unroll
        for (int j = 0; j < 8; ++j) {
            int idx = tid + j * 256;       // 0..2047
            int T   = idx >> 10;
            int rem = idx & 1023;
            int row = rem >> 2;            // 0..255
            int c   = rem & 3;
            cp_async16(s0 + (uint32_t)(G2_BH + T * BTILE_B + row * SROWB + c * 16),
                       Bsrc[T] + (size_t)(n0 + row) * Kd + k0 + c * 8);
        }
        asm volatile("cp.async.commit_group;" ::: "memory");
    };

    load_chunk(0, 0);
    if (nch > 1) load_chunk(1, 1);

    int st = 0;
    int ls = 2 % G2_NSTAGE;

    for (int i = 0; i < nch; ++i) {
        if (i + 1 < nch)
            asm volatile("cp.async.wait_group 1;" ::: "memory");
        else
            asm volatile("cp.async.wait_group 0;" ::: "memory");
        __syncthreads();
        if (i + 2 < nch) {
            load_chunk(i + 2, ls);
            ls = (ls + 1 == G2_NSTAGE) ? 0 : ls + 1;
        }

        const uint32_t sb  = smem_base + (uint32_t)st * G2_STAGE_B;
        const uint32_t sA  = sb + G2_A;
        const uint32_t sBh = sb + G2_BH;
        const uint32_t sBl = sb + G2_BL;

        #pragma unroll
        for (int ks = 0; ks < 2; ++ks) {
            const uint32_t kadd = (uint32_t)(ks * 32);

            uint32_t av[4][4], bh[4][4], bl[4][4];
            #pragma unroll
            for (int mt = 0; mt < 4; ++mt)
                ldsm_x4(av[mt], sA + aoff[mt] + kadd);
            #pragma unroll
            for (int p = 0; p < 4; ++p) {
                ldsm_x4(bh[p], sBh + boff[p] + kadd);
                ldsm_x4(bl[p], sBl + boff[p] + kadd);
            }

            // Pass 1: P*Vhi (32 independent MMAs)
            #pragma unroll
            for (int p = 0; p < 4; ++p)
                #pragma unroll
                for (int mt = 0; mt < 4; ++mt) {
                    mma_f16(acc[mt][2 * p],     av[mt], &bh[p][0]);
                    mma_f16(acc[mt][2 * p + 1], av[mt], &bh[p][2]);
                }
            // Pass 2: P*Vlo
            #pragma unroll
            for (int p = 0; p < 4; ++p)
                #pragma unroll
                for (int mt = 0; mt < 4; ++mt) {
                    mma_f16(acc[mt][2 * p],     av[mt], &bl[p][0]);
                    mma_f16(acc[mt][2 * p + 1], av[mt], &bl[p][2]);
                }
        }

        st = (st + 1 == G2_NSTAGE) ? 0 : st + 1;
    }

    float* Cb = C + (size_t)b * 2048 * (size_t)N;
    #pragma unroll
    for (int mt = 0; mt < 4; ++mt) {
        const int row = m0 + wm + mt * 16 + group;
        #pragma unroll
        for (int nt = 0; nt < 8; ++nt) {
            const int col = n0 + wn + nt * 8 + 2 * tig;
            float2 lo2, hi2;
            lo2.x = acc[mt][nt][0]; lo2.y = acc[mt][nt][1];
            hi2.x = acc[mt][nt][2]; hi2.y = acc[mt][nt][3];
            *(float2*)(Cb + (size_t)row * N + col)       = lo2;
            *(float2*)(Cb + (size_t)(row + 8) * N + col) = hi2;
        }
    }
}

// ---------------------------------------------------------------------------
extern "C" void kernel_launch(void* const* d_in, const int* in_sizes, int n_in,
                              void* d_out, int out_size) {
    const float* q = (const float*)d_in[0];
    const float* v = (const float*)d_in[1];
    float* out = (float*)d_out;

    void *qhi_, *qlo_, *vhi_, *vlo_, *vthi_, *vtlo_, *phi_, *scores_;
    cudaGetSymbolAddress(&qhi_, g_qhi);
    cudaGetSymbolAddress(&qlo_, g_qlo);
    cudaGetSymbolAddress(&vhi_, g_vhi);
    cudaGetSymbolAddress(&vlo_, g_vlo);
    cudaGetSymbolAddress(&vthi_, g_vthi);
    cudaGetSymbolAddress(&vtlo_, g_vtlo);
    cudaGetSymbolAddress(&phi_, g_phi);
    cudaGetSymbolAddress(&scores_, g_scores);

    cudaFuncSetAttribute(hmma_gemm1_kernel,
                         cudaFuncAttributeMaxDynamicSharedMemorySize, G1_SMEM);
    cudaFuncSetAttribute(hmma_gemm2_kernel,
                         cudaFuncAttributeMaxDynamicSharedMemorySize, G2_SMEM);

    // Split Q (bf16 hi/lo)
    {
        int n4 = NB * NQ * ND / 4;
        split_kernel<<<n4 / 256, 256>>>((const float4*)q,
                                        (__nv_bfloat16*)qhi_, (__nv_bfloat16*)qlo_);
    }
    // V: bf16 hi/lo rows + fp16 hi/lo transpose
    {
        dim3 grid(ND / 32, NK / 32, NB);
        v_split_transpose_kernel<<<grid, 256>>>(v,
            (__nv_bfloat16*)vhi_, (__nv_bfloat16*)vlo_,
            (__half*)vthi_, (__half*)vtlo_);
    }
    // S = Q @ V^T   (bf16 3-pass)
    {
        dim3 grid(NK / 256, NQ / 128, NB);    // (8, 16, 4)
        hmma_gemm1_kernel<<<grid, 256, G1_SMEM>>>(
            (const __nv_bfloat16*)qhi_, (const __nv_bfloat16*)qlo_,
            (const __nv_bfloat16*)vhi_, (const __nv_bfloat16*)vlo_,
            (float*)scores_, ND, NK);
    }
    // P = softmax(S) -> fp16
    {
        softmax_kernel<<<NB * NQ, 256>>>((__half*)phi_);
    }
    // O = P @ V   (fp16 2-pass)
    {
        dim3 grid(ND / 256, NQ / 128, NB);    // (4, 16, 4)
        hmma_gemm2_kernel<<<grid, 256, G2_SMEM>>>(
            (const __half*)phi_,
            (const __half*)vthi_, (const __half*)vtlo_,
            out, NK, ND);
    }
}